// round 5
// baseline (speedup 1.0000x reference)
#include <cuda_runtime.h>

#define BATCH 4
#define S_LEN 4096
#define DM    1024
#define DKV   128

// Scratch for projected Q/K/V (no cudaMalloc allowed)
__device__ float g_qp[BATCH * S_LEN * DKV];
__device__ float g_kp[BATCH * S_LEN * DKV];
__device__ float g_vp[BATCH * S_LEN * DKV];

// ---------------------------------------------------------------------------
// Projection GEMM: C[16384,128] = A[16384,1024] @ W[1024,128] + bias[128]
// blockIdx.z selects which projection (0=Q, 1=K, 2=V).
// Tile: BM=128, BN=128, BK=16. 256 threads, 8x8 micro-tile per thread.
// ---------------------------------------------------------------------------
__global__ __launch_bounds__(256, 2)
void proj_kernel(const float* __restrict__ q, const float* __restrict__ k,
                 const float* __restrict__ v,
                 const float* __restrict__ wq, const float* __restrict__ bq,
                 const float* __restrict__ wk, const float* __restrict__ bk,
                 const float* __restrict__ wv, const float* __restrict__ bv)
{
    const float* A; const float* W; const float* bias; float* C;
    if (blockIdx.z == 0)      { A = q; W = wq; bias = bq; C = g_qp; }
    else if (blockIdx.z == 1) { A = k; W = wk; bias = bk; C = g_kp; }
    else                      { A = v; W = wv; bias = bv; C = g_vp; }

    __shared__ float As[16][132];   // k-major (transposed), +4 pad (stride mult of 4)
    __shared__ float Bs[16][128];

    const int tid = threadIdx.x;
    const int ty  = tid >> 4;       // 0..15
    const int tx  = tid & 15;       // 0..15
    const int m0  = blockIdx.x * 128;

    float acc[8][8];
    #pragma unroll
    for (int i = 0; i < 8; i++)
        #pragma unroll
        for (int j = 0; j < 8; j++) acc[i][j] = 0.0f;

    for (int k0 = 0; k0 < DM; k0 += 16) {
        // Load A tile: 128 rows x 16 k -> As[k][m] (scalar transposed stores)
        #pragma unroll
        for (int it = 0; it < 2; it++) {
            int idx = tid + it * 256;            // 0..511 float4s
            int row = idx >> 2;                  // 0..127
            int kq  = (idx & 3) << 2;            // 0,4,8,12
            float4 av = *(const float4*)&A[(size_t)(m0 + row) * DM + k0 + kq];
            As[kq + 0][row] = av.x;
            As[kq + 1][row] = av.y;
            As[kq + 2][row] = av.z;
            As[kq + 3][row] = av.w;
        }
        // Load W tile: 16 rows x 128 cols
        #pragma unroll
        for (int it = 0; it < 2; it++) {
            int idx = tid + it * 256;            // 0..511 float4s
            int kr  = idx >> 5;                  // 0..15
            int c4  = (idx & 31) << 2;           // 0..124
            *(float4*)&Bs[kr][c4] = *(const float4*)&W[(size_t)(k0 + kr) * DKV + c4];
        }
        __syncthreads();

        #pragma unroll
        for (int kk = 0; kk < 16; kk++) {
            float a[8], bb[8];
            // As row stride 132 (mult of 4) -> float4 aligned
            *(float4*)&a[0]  = *(float4*)&As[kk][ty * 8];
            *(float4*)&a[4]  = *(float4*)&As[kk][ty * 8 + 4];
            *(float4*)&bb[0] = *(float4*)&Bs[kk][tx * 8];
            *(float4*)&bb[4] = *(float4*)&Bs[kk][tx * 8 + 4];
            #pragma unroll
            for (int i = 0; i < 8; i++)
                #pragma unroll
                for (int j = 0; j < 8; j++)
                    acc[i][j] += a[i] * bb[j];
        }
        __syncthreads();
    }

    // Epilogue: add bias, store
    float bvec[8];
    *(float4*)&bvec[0] = *(const float4*)&bias[tx * 8];
    *(float4*)&bvec[4] = *(const float4*)&bias[tx * 8 + 4];
    #pragma unroll
    for (int i = 0; i < 8; i++) {
        float4 o0, o1;
        o0.x = acc[i][0] + bvec[0]; o0.y = acc[i][1] + bvec[1];
        o0.z = acc[i][2] + bvec[2]; o0.w = acc[i][3] + bvec[3];
        o1.x = acc[i][4] + bvec[4]; o1.y = acc[i][5] + bvec[5];
        o1.z = acc[i][6] + bvec[6]; o1.w = acc[i][7] + bvec[7];
        size_t base = (size_t)(m0 + ty * 8 + i) * DKV + tx * 8;
        *(float4*)&C[base]     = o0;
        *(float4*)&C[base + 4] = o1;
    }
}

// ---------------------------------------------------------------------------
// Flash attention (fp32, online softmax).
// Grid: (S/64, B). Block: 256 threads (16x16).
// Smem: Qs[64][128], Kst[128][65] (d-major, odd pad: conflict-free transposed
//       stores; loads are SCALAR because stride 65 breaks float4 alignment),
//       Vs[64][128], Ps[64][64] = 115200 bytes dynamic.
// ---------------------------------------------------------------------------
__global__ __launch_bounds__(256, 2)
void attn_kernel(float* __restrict__ out)
{
    extern __shared__ float sm[];
    float* Qs  = sm;                    // 64*128  = 8192
    float* Kst = Qs + 64 * 128;         // 128*65  = 8320
    float* Vs  = Kst + 128 * 65;        // 64*128  = 8192
    float* Ps  = Vs + 64 * 128;         // 64*64   = 4096
                                        // total 28800 floats = 115200 B

    const int b   = blockIdx.y;
    const int q0  = blockIdx.x * 64;
    const int tid = threadIdx.x;
    const int ty  = tid >> 4;           // 0..15
    const int tx  = tid & 15;           // 0..15
    const float scale = 0.08838834764831845f;  // 1/sqrt(128)

    const float* qp = g_qp + (size_t)b * S_LEN * DKV;
    const float* kp = g_kp + (size_t)b * S_LEN * DKV;
    const float* vp = g_vp + (size_t)b * S_LEN * DKV;

    // Load Q tile (pre-scaled)
    #pragma unroll
    for (int it = 0; it < 8; it++) {
        int idx = tid + it * 256;       // 0..2047 float4s
        int r   = idx >> 5;             // 0..63
        int c4  = (idx & 31) << 2;      // 0..124
        float4 qv = *(const float4*)&qp[(size_t)(q0 + r) * DKV + c4];
        qv.x *= scale; qv.y *= scale; qv.z *= scale; qv.w *= scale;
        *(float4*)&Qs[r * 128 + c4] = qv;
    }

    float o[4][8];
    #pragma unroll
    for (int i = 0; i < 4; i++)
        #pragma unroll
        for (int c = 0; c < 8; c++) o[i][c] = 0.0f;
    float m_r[4] = { -1e30f, -1e30f, -1e30f, -1e30f };
    float l_r[4] = { 0.0f, 0.0f, 0.0f, 0.0f };

    for (int kt = 0; kt < S_LEN; kt += 64) {
        __syncthreads();   // previous PV reads done before overwriting K/V

        // Load K tile d-major (transposed, scalar stores) and V row-major
        #pragma unroll
        for (int it = 0; it < 8; it++) {
            int idx = tid + it * 256;
            int r   = idx >> 5;             // key row within tile 0..63
            int c4  = (idx & 31) << 2;      // d 0..124
            float4 kv = *(const float4*)&kp[(size_t)(kt + r) * DKV + c4];
            Kst[(c4 + 0) * 65 + r] = kv.x;
            Kst[(c4 + 1) * 65 + r] = kv.y;
            Kst[(c4 + 2) * 65 + r] = kv.z;
            Kst[(c4 + 3) * 65 + r] = kv.w;
            float4 vv = *(const float4*)&vp[(size_t)(kt + r) * DKV + c4];
            *(float4*)&Vs[r * 128 + c4] = vv;
        }
        __syncthreads();

        // S = (scaled Q) K^T : 4x4 micro-tile
        float s[4][4];
        #pragma unroll
        for (int i = 0; i < 4; i++)
            #pragma unroll
            for (int j = 0; j < 4; j++) s[i][j] = 0.0f;

        for (int d = 0; d < 128; d += 4) {
            float qv[4][4];
            #pragma unroll
            for (int i = 0; i < 4; i++)
                *(float4*)&qv[i][0] = *(float4*)&Qs[(ty * 4 + i) * 128 + d];
            #pragma unroll
            for (int dd = 0; dd < 4; dd++) {
                // SCALAR loads: row base (d+dd)*65 is not 16B-aligned
                const float* krow = &Kst[(d + dd) * 65 + tx * 4];
                float k0 = krow[0], k1 = krow[1], k2 = krow[2], k3 = krow[3];
                #pragma unroll
                for (int i = 0; i < 4; i++) {
                    s[i][0] += qv[i][dd] * k0;
                    s[i][1] += qv[i][dd] * k1;
                    s[i][2] += qv[i][dd] * k2;
                    s[i][3] += qv[i][dd] * k3;
                }
            }
        }

        // Online softmax update (row reduce across 16-lane tx group)
        float alpha[4];
        #pragma unroll
        for (int i = 0; i < 4; i++) {
            float mx = fmaxf(fmaxf(s[i][0], s[i][1]), fmaxf(s[i][2], s[i][3]));
            #pragma unroll
            for (int off = 1; off < 16; off <<= 1)
                mx = fmaxf(mx, __shfl_xor_sync(0xffffffffu, mx, off));
            float mnew = fmaxf(m_r[i], mx);
            alpha[i]   = __expf(m_r[i] - mnew);
            m_r[i]     = mnew;
            float ls = 0.0f;
            #pragma unroll
            for (int j = 0; j < 4; j++) {
                s[i][j] = __expf(s[i][j] - mnew);
                ls += s[i][j];
            }
            #pragma unroll
            for (int off = 1; off < 16; off <<= 1)
                ls += __shfl_xor_sync(0xffffffffu, ls, off);
            l_r[i] = l_r[i] * alpha[i] + ls;
        }

        // Store P, rescale O
        #pragma unroll
        for (int i = 0; i < 4; i++) {
            float4 pv;
            pv.x = s[i][0]; pv.y = s[i][1]; pv.z = s[i][2]; pv.w = s[i][3];
            *(float4*)&Ps[(ty * 4 + i) * 64 + tx * 4] = pv;
        }
        #pragma unroll
        for (int i = 0; i < 4; i++)
            #pragma unroll
            for (int c = 0; c < 8; c++) o[i][c] *= alpha[i];
        __syncthreads();

        // O += P @ V
        for (int kk = 0; kk < 64; kk += 4) {
            float pv[4][4];
            #pragma unroll
            for (int i = 0; i < 4; i++)
                *(float4*)&pv[i][0] = *(float4*)&Ps[(ty * 4 + i) * 64 + kk];
            #pragma unroll
            for (int k2 = 0; k2 < 4; k2++) {
                float vv[8];
                *(float4*)&vv[0] = *(float4*)&Vs[(kk + k2) * 128 + tx * 8];
                *(float4*)&vv[4] = *(float4*)&Vs[(kk + k2) * 128 + tx * 8 + 4];
                #pragma unroll
                for (int i = 0; i < 4; i++)
                    #pragma unroll
                    for (int c = 0; c < 8; c++)
                        o[i][c] += pv[i][k2] * vv[c];
            }
        }
    }

    // Final normalize + store
    #pragma unroll
    for (int i = 0; i < 4; i++) {
        float inv = 1.0f / l_r[i];
        float4 o0, o1;
        o0.x = o[i][0] * inv; o0.y = o[i][1] * inv;
        o0.z = o[i][2] * inv; o0.w = o[i][3] * inv;
        o1.x = o[i][4] * inv; o1.y = o[i][5] * inv;
        o1.z = o[i][6] * inv; o1.w = o[i][7] * inv;
        size_t base = ((size_t)b * S_LEN + q0 + ty * 4 + i) * DKV + tx * 8;
        *(float4*)&out[base]     = o0;
        *(float4*)&out[base + 4] = o1;
    }
}

// ---------------------------------------------------------------------------
extern "C" void kernel_launch(void* const* d_in, const int* in_sizes, int n_in,
                              void* d_out, int out_size)
{
    const float* q  = (const float*)d_in[0];
    const float* k  = (const float*)d_in[1];
    const float* v  = (const float*)d_in[2];
    const float* wq = (const float*)d_in[3];
    const float* bq = (const float*)d_in[4];
    const float* wk = (const float*)d_in[5];
    const float* bk = (const float*)d_in[6];
    const float* wv = (const float*)d_in[7];
    const float* bv = (const float*)d_in[8];
    float* out = (float*)d_out;

    const int smem_bytes = 28800 * (int)sizeof(float);   // 115200
    cudaFuncSetAttribute(attn_kernel,
                         cudaFuncAttributeMaxDynamicSharedMemorySize, smem_bytes);

    // 3 projections: grid (M/128, 1, 3)
    proj_kernel<<<dim3(128, 1, 3), 256>>>(q, k, v, wq, bq, wk, bk, wv, bv);

    // Attention: grid (S/64, B)
    attn_kernel<<<dim3(S_LEN / 64, BATCH), 256, smem_bytes>>>(out);
}

// round 6
// speedup vs baseline: 1.6586x; 1.6586x over previous
#include <cuda_runtime.h>
#include <cstdint>

#define BATCH 4
#define S_LEN 4096
#define DM    1024
#define DKV   128

// Scratch for projected Q/K/V (no cudaMalloc allowed).
// Values stored tf32-rounded (cvt.rna) so attention can MMA them directly.
__device__ float g_qp[BATCH * S_LEN * DKV];   // pre-scaled by 1/sqrt(dk)
__device__ float g_kp[BATCH * S_LEN * DKV];
__device__ float g_vp[BATCH * S_LEN * DKV];

__device__ __forceinline__ uint32_t f2tf32(float f) {
    uint32_t u;
    asm("cvt.rna.tf32.f32 %0, %1;" : "=r"(u) : "f"(f));
    return u;
}

__device__ __forceinline__ void mma_tf32(float& d0, float& d1, float& d2, float& d3,
                                         uint32_t a0, uint32_t a1, uint32_t a2, uint32_t a3,
                                         uint32_t b0, uint32_t b1) {
    asm volatile(
        "mma.sync.aligned.m16n8k8.row.col.f32.tf32.tf32.f32 "
        "{%0,%1,%2,%3}, {%4,%5,%6,%7}, {%8,%9}, {%0,%1,%2,%3};"
        : "+f"(d0), "+f"(d1), "+f"(d2), "+f"(d3)
        : "r"(a0), "r"(a1), "r"(a2), "r"(a3), "r"(b0), "r"(b1));
}

// ---------------------------------------------------------------------------
// Projection GEMM: C[16384,128] = A[16384,1024] @ W[1024,128] + bias
// Epilogue rounds output to tf32 (rna); Q projection also folds in 1/sqrt(dk).
// ---------------------------------------------------------------------------
__global__ __launch_bounds__(256, 2)
void proj_kernel(const float* __restrict__ q, const float* __restrict__ k,
                 const float* __restrict__ v,
                 const float* __restrict__ wq, const float* __restrict__ bq,
                 const float* __restrict__ wk, const float* __restrict__ bk,
                 const float* __restrict__ wv, const float* __restrict__ bv)
{
    const float* A; const float* W; const float* bias; float* C;
    if (blockIdx.z == 0)      { A = q; W = wq; bias = bq; C = g_qp; }
    else if (blockIdx.z == 1) { A = k; W = wk; bias = bk; C = g_kp; }
    else                      { A = v; W = wv; bias = bv; C = g_vp; }
    const float outscale = (blockIdx.z == 0) ? 0.08838834764831845f : 1.0f;

    __shared__ float As[16][132];
    __shared__ float Bs[16][128];

    const int tid = threadIdx.x;
    const int ty  = tid >> 4;
    const int tx  = tid & 15;
    const int m0  = blockIdx.x * 128;

    float acc[8][8];
    #pragma unroll
    for (int i = 0; i < 8; i++)
        #pragma unroll
        for (int j = 0; j < 8; j++) acc[i][j] = 0.0f;

    for (int k0 = 0; k0 < DM; k0 += 16) {
        #pragma unroll
        for (int it = 0; it < 2; it++) {
            int idx = tid + it * 256;
            int row = idx >> 2;
            int kq  = (idx & 3) << 2;
            float4 av = *(const float4*)&A[(size_t)(m0 + row) * DM + k0 + kq];
            As[kq + 0][row] = av.x;
            As[kq + 1][row] = av.y;
            As[kq + 2][row] = av.z;
            As[kq + 3][row] = av.w;
        }
        #pragma unroll
        for (int it = 0; it < 2; it++) {
            int idx = tid + it * 256;
            int kr  = idx >> 5;
            int c4  = (idx & 31) << 2;
            *(float4*)&Bs[kr][c4] = *(const float4*)&W[(size_t)(k0 + kr) * DKV + c4];
        }
        __syncthreads();

        #pragma unroll
        for (int kk = 0; kk < 16; kk++) {
            float a[8], bb[8];
            *(float4*)&a[0]  = *(float4*)&As[kk][ty * 8];
            *(float4*)&a[4]  = *(float4*)&As[kk][ty * 8 + 4];
            *(float4*)&bb[0] = *(float4*)&Bs[kk][tx * 8];
            *(float4*)&bb[4] = *(float4*)&Bs[kk][tx * 8 + 4];
            #pragma unroll
            for (int i = 0; i < 8; i++)
                #pragma unroll
                for (int j = 0; j < 8; j++)
                    acc[i][j] += a[i] * bb[j];
        }
        __syncthreads();
    }

    float bvec[8];
    *(float4*)&bvec[0] = *(const float4*)&bias[tx * 8];
    *(float4*)&bvec[4] = *(const float4*)&bias[tx * 8 + 4];
    #pragma unroll
    for (int i = 0; i < 8; i++) {
        float r[8];
        #pragma unroll
        for (int j = 0; j < 8; j++) {
            float val = (acc[i][j] + bvec[j]) * outscale;
            r[j] = __uint_as_float(f2tf32(val));   // tf32-rounded fp32
        }
        size_t base = (size_t)(m0 + ty * 8 + i) * DKV + tx * 8;
        *(float4*)&C[base]     = *(float4*)&r[0];
        *(float4*)&C[base + 4] = *(float4*)&r[4];
    }
}

// ---------------------------------------------------------------------------
// Flash attention with tf32 mma.sync (m16n8k8).
// Grid: (S/128, B), 256 threads (8 warps). Each warp owns 16 query rows.
// Key tiles of 64. P stays in registers (C-frag -> A-frag via quad shuffles).
// Smem: Qs[128][132], Ks[64][132], Vs[64][136] = 136192 B (1 CTA/SM).
// All fragment LDS patterns are bank-conflict-free by construction.
// ---------------------------------------------------------------------------
#define QS_STR 132
#define KS_STR 132
#define VS_STR 136

__global__ __launch_bounds__(256, 1)
void attn_tc_kernel(float* __restrict__ out)
{
    extern __shared__ float sm[];
    float* Qs = sm;                          // 128*132 = 16896
    float* Ks = Qs + 128 * QS_STR;           // 64*132  = 8448
    float* Vs = Ks + 64 * KS_STR;            // 64*136  = 8704

    const int b    = blockIdx.y;
    const int q0   = blockIdx.x * 128;
    const int tid  = threadIdx.x;
    const int lane = tid & 31;
    const int warp = tid >> 5;
    const int wm   = warp * 16;              // warp's query-row base
    const int qg   = lane >> 2;              // 0..7  (fragment row)
    const int qt   = lane & 3;               // 0..3  (fragment col group)

    const float* qp = g_qp + (size_t)b * S_LEN * DKV;
    const float* kp = g_kp + (size_t)b * S_LEN * DKV;
    const float* vp = g_vp + (size_t)b * S_LEN * DKV;

    // Load Q tile (already tf32-rounded and scaled by proj)
    #pragma unroll
    for (int it = 0; it < 16; it++) {
        int idx = tid + it * 256;            // 0..4095 float4s
        int r   = idx >> 5;                  // 0..127
        int c4  = (idx & 31) << 2;           // 0..124
        *(float4*)&Qs[r * QS_STR + c4] = *(const float4*)&qp[(size_t)(q0 + r) * DKV + c4];
    }

    float o[16][4];
    #pragma unroll
    for (int d = 0; d < 16; d++)
        #pragma unroll
        for (int c = 0; c < 4; c++) o[d][c] = 0.0f;
    float m0 = -1e30f, m1 = -1e30f, l0 = 0.0f, l1 = 0.0f;

    const uint32_t* Qu = (const uint32_t*)Qs;
    const uint32_t* Ku = (const uint32_t*)Ks;
    const uint32_t* Vu = (const uint32_t*)Vs;

    for (int kt = 0; kt < S_LEN; kt += 64) {
        __syncthreads();                     // prior PV reads complete
        // Load K (stride 132) and V (stride 136) tiles
        #pragma unroll
        for (int it = 0; it < 8; it++) {
            int idx = tid + it * 256;        // 0..2047
            int r   = idx >> 5;              // key 0..63
            int c4  = (idx & 31) << 2;       // d 0..124
            *(float4*)&Ks[r * KS_STR + c4] = *(const float4*)&kp[(size_t)(kt + r) * DKV + c4];
            *(float4*)&Vs[r * VS_STR + c4] = *(const float4*)&vp[(size_t)(kt + r) * DKV + c4];
        }
        __syncthreads();

        // ---- S = Q K^T : 8 n-fragments (64 keys), 16 k-steps (d=128) ----
        float s[8][4];
        #pragma unroll
        for (int nf = 0; nf < 8; nf++)
            #pragma unroll
            for (int c = 0; c < 4; c++) s[nf][c] = 0.0f;

        #pragma unroll
        for (int k = 0; k < 16; k++) {
            uint32_t a0 = Qu[(wm + qg)     * QS_STR + k * 8 + qt];
            uint32_t a1 = Qu[(wm + qg + 8) * QS_STR + k * 8 + qt];
            uint32_t a2 = Qu[(wm + qg)     * QS_STR + k * 8 + qt + 4];
            uint32_t a3 = Qu[(wm + qg + 8) * QS_STR + k * 8 + qt + 4];
            #pragma unroll
            for (int nf = 0; nf < 8; nf++) {
                uint32_t b0 = Ku[(nf * 8 + qg) * KS_STR + k * 8 + qt];
                uint32_t b1 = Ku[(nf * 8 + qg) * KS_STR + k * 8 + qt + 4];
                mma_tf32(s[nf][0], s[nf][1], s[nf][2], s[nf][3], a0, a1, a2, a3, b0, b1);
            }
        }

        // ---- online softmax (rows qg and qg+8; quad = 4 lanes per row) ----
        float mx0 = -1e30f, mx1 = -1e30f;
        #pragma unroll
        for (int nf = 0; nf < 8; nf++) {
            mx0 = fmaxf(mx0, fmaxf(s[nf][0], s[nf][1]));
            mx1 = fmaxf(mx1, fmaxf(s[nf][2], s[nf][3]));
        }
        mx0 = fmaxf(mx0, __shfl_xor_sync(0xffffffffu, mx0, 1));
        mx0 = fmaxf(mx0, __shfl_xor_sync(0xffffffffu, mx0, 2));
        mx1 = fmaxf(mx1, __shfl_xor_sync(0xffffffffu, mx1, 1));
        mx1 = fmaxf(mx1, __shfl_xor_sync(0xffffffffu, mx1, 2));

        float mn0 = fmaxf(m0, mx0);
        float mn1 = fmaxf(m1, mx1);
        float alpha0 = __expf(m0 - mn0);
        float alpha1 = __expf(m1 - mn1);
        m0 = mn0; m1 = mn1;

        float ls0 = 0.0f, ls1 = 0.0f;
        #pragma unroll
        for (int nf = 0; nf < 8; nf++) {
            s[nf][0] = __expf(s[nf][0] - mn0);
            s[nf][1] = __expf(s[nf][1] - mn0);
            s[nf][2] = __expf(s[nf][2] - mn1);
            s[nf][3] = __expf(s[nf][3] - mn1);
            ls0 += s[nf][0] + s[nf][1];
            ls1 += s[nf][2] + s[nf][3];
        }
        ls0 += __shfl_xor_sync(0xffffffffu, ls0, 1);
        ls0 += __shfl_xor_sync(0xffffffffu, ls0, 2);
        ls1 += __shfl_xor_sync(0xffffffffu, ls1, 1);
        ls1 += __shfl_xor_sync(0xffffffffu, ls1, 2);
        l0 = l0 * alpha0 + ls0;
        l1 = l1 * alpha1 + ls1;

        #pragma unroll
        for (int d = 0; d < 16; d++) {
            o[d][0] *= alpha0; o[d][1] *= alpha0;
            o[d][2] *= alpha1; o[d][3] *= alpha1;
        }

        // ---- O += P V : convert each P C-frag to A-frag via quad shuffles ----
        const int mo = (lane & ~3) | (qt >> 1);       // owner of col qt
        const int m2 = mo + 2;                        // owner of col qt+4
        const bool odd = (qt & 1);
        #pragma unroll
        for (int kf = 0; kf < 8; kf++) {
            float c0 = s[kf][0], c1 = s[kf][1], c2 = s[kf][2], c3 = s[kf][3];
            float t00 = __shfl_sync(0xffffffffu, c0, mo);
            float t01 = __shfl_sync(0xffffffffu, c1, mo);
            float t02 = __shfl_sync(0xffffffffu, c2, mo);
            float t03 = __shfl_sync(0xffffffffu, c3, mo);
            float t10 = __shfl_sync(0xffffffffu, c0, m2);
            float t11 = __shfl_sync(0xffffffffu, c1, m2);
            float t12 = __shfl_sync(0xffffffffu, c2, m2);
            float t13 = __shfl_sync(0xffffffffu, c3, m2);
            uint32_t a0 = f2tf32(odd ? t01 : t00);    // P(r,    qt)
            uint32_t a1 = f2tf32(odd ? t03 : t02);    // P(r+8,  qt)
            uint32_t a2 = f2tf32(odd ? t11 : t10);    // P(r,    qt+4)
            uint32_t a3 = f2tf32(odd ? t13 : t12);    // P(r+8,  qt+4)
            #pragma unroll
            for (int df = 0; df < 16; df++) {
                uint32_t b0 = Vu[(kf * 8 + qt)     * VS_STR + df * 8 + qg];
                uint32_t b1 = Vu[(kf * 8 + qt + 4) * VS_STR + df * 8 + qg];
                mma_tf32(o[df][0], o[df][1], o[df][2], o[df][3], a0, a1, a2, a3, b0, b1);
            }
        }
    }

    // ---- normalize and store ----
    float inv0 = 1.0f / l0;
    float inv1 = 1.0f / l1;
    #pragma unroll
    for (int df = 0; df < 16; df++) {
        size_t row0 = (size_t)b * S_LEN + q0 + wm + qg;
        size_t col  = df * 8 + 2 * qt;
        float2 w0 = make_float2(o[df][0] * inv0, o[df][1] * inv0);
        float2 w1 = make_float2(o[df][2] * inv1, o[df][3] * inv1);
        *(float2*)&out[row0 * DKV + col]       = w0;
        *(float2*)&out[(row0 + 8) * DKV + col] = w1;
    }
}

// ---------------------------------------------------------------------------
extern "C" void kernel_launch(void* const* d_in, const int* in_sizes, int n_in,
                              void* d_out, int out_size)
{
    const float* q  = (const float*)d_in[0];
    const float* k  = (const float*)d_in[1];
    const float* v  = (const float*)d_in[2];
    const float* wq = (const float*)d_in[3];
    const float* bq = (const float*)d_in[4];
    const float* wk = (const float*)d_in[5];
    const float* bk = (const float*)d_in[6];
    const float* wv = (const float*)d_in[7];
    const float* bv = (const float*)d_in[8];
    float* out = (float*)d_out;

    const int smem_bytes = (128 * QS_STR + 64 * KS_STR + 64 * VS_STR) * (int)sizeof(float); // 136192
    cudaFuncSetAttribute(attn_tc_kernel,
                         cudaFuncAttributeMaxDynamicSharedMemorySize, smem_bytes);

    proj_kernel<<<dim3(128, 1, 3), 256>>>(q, k, v, wq, bq, wk, bk, wv, bv);
    attn_tc_kernel<<<dim3(S_LEN / 128, BATCH), 256, smem_bytes>>>(out);
}

// round 7
// speedup vs baseline: 3.3392x; 2.0133x over previous
#include <cuda_runtime.h>
#include <cstdint>

#define BATCH 4
#define S_LEN 4096
#define DM    1024
#define DKV   128

// Scratch for projected Q/K/V (tf32-rounded fp32; Q pre-scaled by 1/sqrt(dk))
__device__ float g_qp[BATCH * S_LEN * DKV];
__device__ float g_kp[BATCH * S_LEN * DKV];
__device__ float g_vp[BATCH * S_LEN * DKV];

__device__ __forceinline__ uint32_t f2tf32(float f) {
    uint32_t u;
    asm("cvt.rna.tf32.f32 %0, %1;" : "=r"(u) : "f"(f));
    return u;
}

__device__ __forceinline__ void mma_tf32(float& d0, float& d1, float& d2, float& d3,
                                         uint32_t a0, uint32_t a1, uint32_t a2, uint32_t a3,
                                         uint32_t b0, uint32_t b1) {
    asm volatile(
        "mma.sync.aligned.m16n8k8.row.col.f32.tf32.tf32.f32 "
        "{%0,%1,%2,%3}, {%4,%5,%6,%7}, {%8,%9}, {%0,%1,%2,%3};"
        : "+f"(d0), "+f"(d1), "+f"(d2), "+f"(d3)
        : "r"(a0), "r"(a1), "r"(a2), "r"(a3), "r"(b0), "r"(b1));
}

// ---------------------------------------------------------------------------
// Projection GEMM via tf32 MMA: C[16384,128] = A[16384,1024] @ W[1024,128]+b
// BM=128, BN=128, BK=32. 8 warps: 4 m-groups x 2 n-halves.
// A smem stride 36 (bank perm 4*qg+qt), W smem stride 136 (bank perm 8*qt+qg).
// ---------------------------------------------------------------------------
#define AT_STR 36
#define WT_STR 136

__global__ __launch_bounds__(256, 2)
void proj_tc_kernel(const float* __restrict__ q, const float* __restrict__ k,
                    const float* __restrict__ v,
                    const float* __restrict__ wq, const float* __restrict__ bq,
                    const float* __restrict__ wk, const float* __restrict__ bk,
                    const float* __restrict__ wv, const float* __restrict__ bv)
{
    const float* A; const float* W; const float* bias; float* C;
    if (blockIdx.z == 0)      { A = q; W = wq; bias = bq; C = g_qp; }
    else if (blockIdx.z == 1) { A = k; W = wk; bias = bk; C = g_kp; }
    else                      { A = v; W = wv; bias = bv; C = g_vp; }
    const float outscale = (blockIdx.z == 0) ? 0.08838834764831845f : 1.0f;

    __shared__ uint32_t At[128 * AT_STR];  // 18432 B
    __shared__ uint32_t Wt[32 * WT_STR];   // 17408 B

    const int tid  = threadIdx.x;
    const int lane = tid & 31;
    const int warp = tid >> 5;
    const int mg   = warp >> 1;            // 0..3  (32-row group)
    const int ng   = warp & 1;             // 0..1  (64-col half)
    const int qg   = lane >> 2;            // 0..7
    const int qt   = lane & 3;             // 0..3
    const int m0   = blockIdx.x * 128;

    float acc[2][8][4];
    #pragma unroll
    for (int mi = 0; mi < 2; mi++)
        #pragma unroll
        for (int nf = 0; nf < 8; nf++)
            #pragma unroll
            for (int c = 0; c < 4; c++) acc[mi][nf][c] = 0.0f;

    for (int k0 = 0; k0 < DM; k0 += 32) {
        __syncthreads();
        // A tile: 128 rows x 32 k, convert to tf32 on store
        #pragma unroll
        for (int it = 0; it < 4; it++) {
            int idx = tid + it * 256;          // 0..1023 float4s
            int row = idx >> 3;                // 0..127
            int kq  = (idx & 7) << 2;          // 0..28
            float4 av = *(const float4*)&A[(size_t)(m0 + row) * DM + k0 + kq];
            uint4 u = make_uint4(f2tf32(av.x), f2tf32(av.y), f2tf32(av.z), f2tf32(av.w));
            *(uint4*)&At[row * AT_STR + kq] = u;
        }
        // W tile: 32 k x 128 cols
        #pragma unroll
        for (int it = 0; it < 4; it++) {
            int idx = tid + it * 256;
            int kr  = idx >> 5;                // 0..31
            int c4  = (idx & 31) << 2;         // 0..124
            float4 wv = *(const float4*)&W[(size_t)(k0 + kr) * DKV + c4];
            uint4 u = make_uint4(f2tf32(wv.x), f2tf32(wv.y), f2tf32(wv.z), f2tf32(wv.w));
            *(uint4*)&Wt[kr * WT_STR + c4] = u;
        }
        __syncthreads();

        #pragma unroll
        for (int ks = 0; ks < 4; ks++) {
            uint32_t a[2][4];
            #pragma unroll
            for (int mi = 0; mi < 2; mi++) {
                int r = mg * 32 + mi * 16 + qg;
                a[mi][0] = At[r * AT_STR + ks * 8 + qt];
                a[mi][1] = At[(r + 8) * AT_STR + ks * 8 + qt];
                a[mi][2] = At[r * AT_STR + ks * 8 + qt + 4];
                a[mi][3] = At[(r + 8) * AT_STR + ks * 8 + qt + 4];
            }
            #pragma unroll
            for (int nf = 0; nf < 8; nf++) {
                uint32_t b0 = Wt[(ks * 8 + qt) * WT_STR + ng * 64 + nf * 8 + qg];
                uint32_t b1 = Wt[(ks * 8 + qt + 4) * WT_STR + ng * 64 + nf * 8 + qg];
                #pragma unroll
                for (int mi = 0; mi < 2; mi++)
                    mma_tf32(acc[mi][nf][0], acc[mi][nf][1], acc[mi][nf][2], acc[mi][nf][3],
                             a[mi][0], a[mi][1], a[mi][2], a[mi][3], b0, b1);
            }
        }
    }

    // Epilogue: bias + scale + tf32 rounding, store
    #pragma unroll
    for (int nf = 0; nf < 8; nf++) {
        int col = ng * 64 + nf * 8 + 2 * qt;
        float bv0 = bias[col];
        float bv1 = bias[col + 1];
        #pragma unroll
        for (int mi = 0; mi < 2; mi++) {
            int row = m0 + mg * 32 + mi * 16 + qg;
            float2 w0, w1;
            w0.x = __uint_as_float(f2tf32((acc[mi][nf][0] + bv0) * outscale));
            w0.y = __uint_as_float(f2tf32((acc[mi][nf][1] + bv1) * outscale));
            w1.x = __uint_as_float(f2tf32((acc[mi][nf][2] + bv0) * outscale));
            w1.y = __uint_as_float(f2tf32((acc[mi][nf][3] + bv1) * outscale));
            *(float2*)&C[(size_t)row * DKV + col]       = w0;
            *(float2*)&C[(size_t)(row + 8) * DKV + col] = w1;
        }
    }
}

// ---------------------------------------------------------------------------
// Flash attention, tf32 mma, split-key warps.
// Grid: (S/64, B), 256 threads (8 warps), 2 CTAs/SM.
// Warp w: m-group mg=w&3 (16 q-rows), key-half kh=w>>2 (32 of 64 keys/tile).
// Each warp keeps private online-softmax state; halves merged once at end.
// Smem: Qs[64][132] + Ks[64][132] + Vs[64][136] = 102400 B.
// ---------------------------------------------------------------------------
#define QS_STR 132
#define KS_STR 132
#define VS_STR 136

__global__ __launch_bounds__(256, 2)
void attn_tc_kernel(float* __restrict__ out)
{
    extern __shared__ float sm[];
    float* Qs = sm;                          // 64*132 = 8448
    float* Ks = Qs + 64 * QS_STR;            // 8448
    float* Vs = Ks + 64 * KS_STR;            // 8704   (total 25600 floats)

    const int b    = blockIdx.y;
    const int q0   = blockIdx.x * 64;
    const int tid  = threadIdx.x;
    const int lane = tid & 31;
    const int warp = tid >> 5;
    const int mg   = warp & 3;               // q-row group
    const int kh   = warp >> 2;              // key half (0/1)
    const int wm   = mg * 16;
    const int qg   = lane >> 2;
    const int qt   = lane & 3;

    const float* qp = g_qp + (size_t)b * S_LEN * DKV;
    const float* kp = g_kp + (size_t)b * S_LEN * DKV;
    const float* vp = g_vp + (size_t)b * S_LEN * DKV;

    // Load Q tile (64 rows)
    #pragma unroll
    for (int it = 0; it < 8; it++) {
        int idx = tid + it * 256;            // 0..2047 float4s
        int r   = idx >> 5;                  // 0..63
        int c4  = (idx & 31) << 2;
        *(float4*)&Qs[r * QS_STR + c4] = *(const float4*)&qp[(size_t)(q0 + r) * DKV + c4];
    }

    float o[16][4];
    #pragma unroll
    for (int d = 0; d < 16; d++)
        #pragma unroll
        for (int c = 0; c < 4; c++) o[d][c] = 0.0f;
    float m0 = -1e30f, m1 = -1e30f, l0 = 0.0f, l1 = 0.0f;

    const uint32_t* Qu = (const uint32_t*)Qs;
    const uint32_t* Ku = (const uint32_t*)Ks;
    const uint32_t* Vu = (const uint32_t*)Vs;

    for (int kt = 0; kt < S_LEN; kt += 64) {
        __syncthreads();
        #pragma unroll
        for (int it = 0; it < 8; it++) {
            int idx = tid + it * 256;
            int r   = idx >> 5;
            int c4  = (idx & 31) << 2;
            *(float4*)&Ks[r * KS_STR + c4] = *(const float4*)&kp[(size_t)(kt + r) * DKV + c4];
            *(float4*)&Vs[r * VS_STR + c4] = *(const float4*)&vp[(size_t)(kt + r) * DKV + c4];
        }
        __syncthreads();

        // S = Q K^T over this warp's 32-key half (4 n-frags)
        float s[4][4];
        #pragma unroll
        for (int nf = 0; nf < 4; nf++)
            #pragma unroll
            for (int c = 0; c < 4; c++) s[nf][c] = 0.0f;

        #pragma unroll
        for (int k = 0; k < 16; k++) {
            uint32_t a0 = Qu[(wm + qg)     * QS_STR + k * 8 + qt];
            uint32_t a1 = Qu[(wm + qg + 8) * QS_STR + k * 8 + qt];
            uint32_t a2 = Qu[(wm + qg)     * QS_STR + k * 8 + qt + 4];
            uint32_t a3 = Qu[(wm + qg + 8) * QS_STR + k * 8 + qt + 4];
            #pragma unroll
            for (int nf = 0; nf < 4; nf++) {
                uint32_t b0 = Ku[(kh * 32 + nf * 8 + qg) * KS_STR + k * 8 + qt];
                uint32_t b1 = Ku[(kh * 32 + nf * 8 + qg) * KS_STR + k * 8 + qt + 4];
                mma_tf32(s[nf][0], s[nf][1], s[nf][2], s[nf][3], a0, a1, a2, a3, b0, b1);
            }
        }

        // online softmax over this warp's keys (quad reduce)
        float mx0 = -1e30f, mx1 = -1e30f;
        #pragma unroll
        for (int nf = 0; nf < 4; nf++) {
            mx0 = fmaxf(mx0, fmaxf(s[nf][0], s[nf][1]));
            mx1 = fmaxf(mx1, fmaxf(s[nf][2], s[nf][3]));
        }
        mx0 = fmaxf(mx0, __shfl_xor_sync(0xffffffffu, mx0, 1));
        mx0 = fmaxf(mx0, __shfl_xor_sync(0xffffffffu, mx0, 2));
        mx1 = fmaxf(mx1, __shfl_xor_sync(0xffffffffu, mx1, 1));
        mx1 = fmaxf(mx1, __shfl_xor_sync(0xffffffffu, mx1, 2));

        float mn0 = fmaxf(m0, mx0);
        float mn1 = fmaxf(m1, mx1);
        float alpha0 = __expf(m0 - mn0);
        float alpha1 = __expf(m1 - mn1);
        m0 = mn0; m1 = mn1;

        float ls0 = 0.0f, ls1 = 0.0f;
        #pragma unroll
        for (int nf = 0; nf < 4; nf++) {
            s[nf][0] = __expf(s[nf][0] - mn0);
            s[nf][1] = __expf(s[nf][1] - mn0);
            s[nf][2] = __expf(s[nf][2] - mn1);
            s[nf][3] = __expf(s[nf][3] - mn1);
            ls0 += s[nf][0] + s[nf][1];
            ls1 += s[nf][2] + s[nf][3];
        }
        ls0 += __shfl_xor_sync(0xffffffffu, ls0, 1);
        ls0 += __shfl_xor_sync(0xffffffffu, ls0, 2);
        ls1 += __shfl_xor_sync(0xffffffffu, ls1, 1);
        ls1 += __shfl_xor_sync(0xffffffffu, ls1, 2);
        l0 = l0 * alpha0 + ls0;
        l1 = l1 * alpha1 + ls1;

        #pragma unroll
        for (int d = 0; d < 16; d++) {
            o[d][0] *= alpha0; o[d][1] *= alpha0;
            o[d][2] *= alpha1; o[d][3] *= alpha1;
        }

        // O += P V (this warp's 32 keys: 4 k-frags)
        const int mo  = (lane & ~3) | (qt >> 1);
        const int m2  = mo + 2;
        const bool odd = (qt & 1);
        #pragma unroll
        for (int kf = 0; kf < 4; kf++) {
            float c0 = s[kf][0], c1 = s[kf][1], c2 = s[kf][2], c3 = s[kf][3];
            float t00 = __shfl_sync(0xffffffffu, c0, mo);
            float t01 = __shfl_sync(0xffffffffu, c1, mo);
            float t02 = __shfl_sync(0xffffffffu, c2, mo);
            float t03 = __shfl_sync(0xffffffffu, c3, mo);
            float t10 = __shfl_sync(0xffffffffu, c0, m2);
            float t11 = __shfl_sync(0xffffffffu, c1, m2);
            float t12 = __shfl_sync(0xffffffffu, c2, m2);
            float t13 = __shfl_sync(0xffffffffu, c3, m2);
            uint32_t a0 = f2tf32(odd ? t01 : t00);
            uint32_t a1 = f2tf32(odd ? t03 : t02);
            uint32_t a2 = f2tf32(odd ? t11 : t10);
            uint32_t a3 = f2tf32(odd ? t13 : t12);
            #pragma unroll
            for (int df = 0; df < 16; df++) {
                uint32_t b0 = Vu[(kh * 32 + kf * 8 + qt)     * VS_STR + df * 8 + qg];
                uint32_t b1 = Vu[(kh * 32 + kf * 8 + qt + 4) * VS_STR + df * 8 + qg];
                mma_tf32(o[df][0], o[df][1], o[df][2], o[df][3], a0, a1, a2, a3, b0, b1);
            }
        }
    }

    // ---- merge the two key-halves (reuse Qs/Ks smem) ----
    __syncthreads();
    float* Ms = Qs;                 // 4 groups * 16 rows * 128 cols = 8192 floats
    float* Lm = Ks;                 // 64 floats
    float* Ll = Ks + 64;            // 64 floats

    if (kh == 1) {
        #pragma unroll
        for (int df = 0; df < 16; df++) {
            int col = df * 8 + 2 * qt;
            Ms[mg * 2048 + qg * 128 + col]           = o[df][0];
            Ms[mg * 2048 + qg * 128 + col + 1]       = o[df][1];
            Ms[mg * 2048 + (qg + 8) * 128 + col]     = o[df][2];
            Ms[mg * 2048 + (qg + 8) * 128 + col + 1] = o[df][3];
        }
        if (qt == 0) {
            Lm[mg * 16 + qg]     = m0;  Ll[mg * 16 + qg]     = l0;
            Lm[mg * 16 + qg + 8] = m1;  Ll[mg * 16 + qg + 8] = l1;
        }
    }
    __syncthreads();

    if (kh == 0) {
        float mb0 = Lm[mg * 16 + qg],     lb0 = Ll[mg * 16 + qg];
        float mb1 = Lm[mg * 16 + qg + 8], lb1 = Ll[mg * 16 + qg + 8];
        float mn0 = fmaxf(m0, mb0), mn1 = fmaxf(m1, mb1);
        float ea0 = __expf(m0 - mn0),  eb0 = __expf(mb0 - mn0);
        float ea1 = __expf(m1 - mn1),  eb1 = __expf(mb1 - mn1);
        float inv0 = 1.0f / (l0 * ea0 + lb0 * eb0);
        float inv1 = 1.0f / (l1 * ea1 + lb1 * eb1);

        #pragma unroll
        for (int df = 0; df < 16; df++) {
            int col = df * 8 + 2 * qt;
            float ob0 = Ms[mg * 2048 + qg * 128 + col];
            float ob1 = Ms[mg * 2048 + qg * 128 + col + 1];
            float ob2 = Ms[mg * 2048 + (qg + 8) * 128 + col];
            float ob3 = Ms[mg * 2048 + (qg + 8) * 128 + col + 1];
            size_t row0 = (size_t)b * S_LEN + q0 + wm + qg;
            float2 w0, w1;
            w0.x = (o[df][0] * ea0 + ob0 * eb0) * inv0;
            w0.y = (o[df][1] * ea0 + ob1 * eb0) * inv0;
            w1.x = (o[df][2] * ea1 + ob2 * eb1) * inv1;
            w1.y = (o[df][3] * ea1 + ob3 * eb1) * inv1;
            *(float2*)&out[row0 * DKV + col]       = w0;
            *(float2*)&out[(row0 + 8) * DKV + col] = w1;
        }
    }
}

// ---------------------------------------------------------------------------
extern "C" void kernel_launch(void* const* d_in, const int* in_sizes, int n_in,
                              void* d_out, int out_size)
{
    const float* q  = (const float*)d_in[0];
    const float* k  = (const float*)d_in[1];
    const float* v  = (const float*)d_in[2];
    const float* wq = (const float*)d_in[3];
    const float* bq = (const float*)d_in[4];
    const float* wk = (const float*)d_in[5];
    const float* bk = (const float*)d_in[6];
    const float* wv = (const float*)d_in[7];
    const float* bv = (const float*)d_in[8];
    float* out = (float*)d_out;

    const int smem_bytes = (64 * QS_STR + 64 * KS_STR + 64 * VS_STR) * (int)sizeof(float); // 102400
    cudaFuncSetAttribute(attn_tc_kernel,
                         cudaFuncAttributeMaxDynamicSharedMemorySize, smem_bytes);

    proj_tc_kernel<<<dim3(128, 1, 3), 256>>>(q, k, v, wq, bq, wk, bk, wv, bv);
    attn_tc_kernel<<<dim3(S_LEN / 64, BATCH), 256, smem_bytes>>>(out);
}

// round 9
// speedup vs baseline: 5.5823x; 1.6717x over previous
#include <cuda_runtime.h>
#include <cuda_fp16.h>
#include <cstdint>

#define BATCH 4
#define S_LEN 4096
#define DM    1024
#define DKV   128

// Scratch (no cudaMalloc allowed). Q/K projected -> fp16 (rn), V -> fp32.
__device__ __half g_qph[BATCH * S_LEN * DKV];   // pre-scaled by 1/sqrt(dk)
__device__ __half g_kph[BATCH * S_LEN * DKV];
__device__ float  g_vp [BATCH * S_LEN * DKV];

__device__ __forceinline__ uint32_t f2tf32(float f) {
    uint32_t u;
    asm("cvt.rna.tf32.f32 %0, %1;" : "=r"(u) : "f"(f));
    return u;
}
__device__ __forceinline__ uint32_t pack_f16x2(float hi, float lo) {
    uint32_t r;
    asm("cvt.rn.f16x2.f32 %0, %1, %2;" : "=r"(r) : "f"(hi), "f"(lo));
    return r;
}
__device__ __forceinline__ void cp16(uint32_t dst, const void* src) {
    asm volatile("cp.async.ca.shared.global [%0], [%1], 16;" :: "r"(dst), "l"(src) : "memory");
}
__device__ __forceinline__ uint32_t smem_u32(const void* p) {
    return (uint32_t)__cvta_generic_to_shared(p);
}
#define CP_COMMIT()  asm volatile("cp.async.commit_group;" ::: "memory")
#define CP_WAIT(n)   asm volatile("cp.async.wait_group %0;" :: "n"(n) : "memory")

__device__ __forceinline__ void mma_tf32(float& d0, float& d1, float& d2, float& d3,
                                         uint32_t a0, uint32_t a1, uint32_t a2, uint32_t a3,
                                         uint32_t b0, uint32_t b1) {
    asm volatile(
        "mma.sync.aligned.m16n8k8.row.col.f32.tf32.tf32.f32 "
        "{%0,%1,%2,%3}, {%4,%5,%6,%7}, {%8,%9}, {%0,%1,%2,%3};"
        : "+f"(d0), "+f"(d1), "+f"(d2), "+f"(d3)
        : "r"(a0), "r"(a1), "r"(a2), "r"(a3), "r"(b0), "r"(b1));
}
__device__ __forceinline__ void mma_f16(float& d0, float& d1, float& d2, float& d3,
                                        uint32_t a0, uint32_t a1, uint32_t a2, uint32_t a3,
                                        uint32_t b0, uint32_t b1) {
    asm volatile(
        "mma.sync.aligned.m16n8k16.row.col.f32.f16.f16.f32 "
        "{%0,%1,%2,%3}, {%4,%5,%6,%7}, {%8,%9}, {%0,%1,%2,%3};"
        : "+f"(d0), "+f"(d1), "+f"(d2), "+f"(d3)
        : "r"(a0), "r"(a1), "r"(a2), "r"(a3), "r"(b0), "r"(b1));
}

// ---------------------------------------------------------------------------
// Projection GEMM via tf32 MMA, register double-buffered gmem loads,
// EXPLICIT rna tf32 conversion at smem store (unbiased — raw-bits truncation
// in the MMA is biased and costs ~1e-3 on a 1024-deep dot product).
// BM=128, BN=128, BK=32. 8 warps: 4 m-groups x 2 n-halves.
// Q/K outputs stored fp16 (rn); V output stored fp32.
// ---------------------------------------------------------------------------
#define AT_STR 36
#define WT_STR 136

__global__ __launch_bounds__(256, 2)
void proj_tc_kernel(const float* __restrict__ q, const float* __restrict__ k,
                    const float* __restrict__ v,
                    const float* __restrict__ wq, const float* __restrict__ bq,
                    const float* __restrict__ wk, const float* __restrict__ bk,
                    const float* __restrict__ wv, const float* __restrict__ bv)
{
    const float* A; const float* W; const float* bias;
    __half* Ch = nullptr; float* Cf = nullptr;
    if (blockIdx.z == 0)      { A = q; W = wq; bias = bq; Ch = g_qph; }
    else if (blockIdx.z == 1) { A = k; W = wk; bias = bk; Ch = g_kph; }
    else                      { A = v; W = wv; bias = bv; Cf = g_vp; }
    const float outscale = (blockIdx.z == 0) ? 0.08838834764831845f : 1.0f;

    __shared__ uint32_t At[128 * AT_STR];   // 18432 B, tf32(rna)
    __shared__ uint32_t Wt[32 * WT_STR];    // 17408 B, tf32(rna)

    const int tid  = threadIdx.x;
    const int lane = tid & 31;
    const int warp = tid >> 5;
    const int mg   = warp >> 1;
    const int ng   = warp & 1;
    const int qg   = lane >> 2;
    const int qt   = lane & 3;
    const int m0   = blockIdx.x * 128;

    float acc[2][8][4];
    #pragma unroll
    for (int mi = 0; mi < 2; mi++)
        #pragma unroll
        for (int nf = 0; nf < 8; nf++)
            #pragma unroll
            for (int c = 0; c < 4; c++) acc[mi][nf][c] = 0.0f;

    float4 abuf[4], wbuf[4];
    #pragma unroll
    for (int i = 0; i < 4; i++) {
        int id  = tid + i * 256;
        int row = id >> 3;                 // 0..127
        int kq  = (id & 7) << 2;           // 0..28
        abuf[i] = *(const float4*)&A[(size_t)(m0 + row) * DM + kq];
    }
    #pragma unroll
    for (int i = 0; i < 4; i++) {
        int id  = tid + i * 256;
        int kr  = id >> 5;                 // 0..31
        int c4  = (id & 31) << 2;          // 0..124
        wbuf[i] = *(const float4*)&W[(size_t)kr * DKV + c4];
    }

    for (int k0 = 0; k0 < DM; k0 += 32) {
        __syncthreads();                   // prior compute reads done
        // store regs -> smem with rna tf32 conversion
        #pragma unroll
        for (int i = 0; i < 4; i++) {
            int id  = tid + i * 256;
            int row = id >> 3;
            int kq  = (id & 7) << 2;
            uint4 u = make_uint4(f2tf32(abuf[i].x), f2tf32(abuf[i].y),
                                 f2tf32(abuf[i].z), f2tf32(abuf[i].w));
            *(uint4*)&At[row * AT_STR + kq] = u;
        }
        #pragma unroll
        for (int i = 0; i < 4; i++) {
            int id  = tid + i * 256;
            int kr  = id >> 5;
            int c4  = (id & 31) << 2;
            uint4 u = make_uint4(f2tf32(wbuf[i].x), f2tf32(wbuf[i].y),
                                 f2tf32(wbuf[i].z), f2tf32(wbuf[i].w));
            *(uint4*)&Wt[kr * WT_STR + c4] = u;
        }
        __syncthreads();

        // issue next tile's gmem loads (latency hidden under MMAs below)
        if (k0 + 32 < DM) {
            #pragma unroll
            for (int i = 0; i < 4; i++) {
                int id  = tid + i * 256;
                int row = id >> 3;
                int kq  = (id & 7) << 2;
                abuf[i] = *(const float4*)&A[(size_t)(m0 + row) * DM + k0 + 32 + kq];
            }
            #pragma unroll
            for (int i = 0; i < 4; i++) {
                int id  = tid + i * 256;
                int kr  = id >> 5;
                int c4  = (id & 31) << 2;
                wbuf[i] = *(const float4*)&W[(size_t)(k0 + 32 + kr) * DKV + c4];
            }
        }

        #pragma unroll
        for (int ks = 0; ks < 4; ks++) {
            uint32_t a[2][4];
            #pragma unroll
            for (int mi = 0; mi < 2; mi++) {
                int r = mg * 32 + mi * 16 + qg;
                a[mi][0] = At[r * AT_STR + ks * 8 + qt];
                a[mi][1] = At[(r + 8) * AT_STR + ks * 8 + qt];
                a[mi][2] = At[r * AT_STR + ks * 8 + qt + 4];
                a[mi][3] = At[(r + 8) * AT_STR + ks * 8 + qt + 4];
            }
            #pragma unroll
            for (int nf = 0; nf < 8; nf++) {
                uint32_t b0 = Wt[(ks * 8 + qt)     * WT_STR + ng * 64 + nf * 8 + qg];
                uint32_t b1 = Wt[(ks * 8 + qt + 4) * WT_STR + ng * 64 + nf * 8 + qg];
                #pragma unroll
                for (int mi = 0; mi < 2; mi++)
                    mma_tf32(acc[mi][nf][0], acc[mi][nf][1], acc[mi][nf][2], acc[mi][nf][3],
                             a[mi][0], a[mi][1], a[mi][2], a[mi][3], b0, b1);
            }
        }
    }

    // Epilogue: bias + scale; Q/K -> fp16 (rn), V -> fp32
    #pragma unroll
    for (int nf = 0; nf < 8; nf++) {
        int col = ng * 64 + nf * 8 + 2 * qt;
        float bv0 = bias[col];
        float bv1 = bias[col + 1];
        #pragma unroll
        for (int mi = 0; mi < 2; mi++) {
            int row = m0 + mg * 32 + mi * 16 + qg;
            float x0 = (acc[mi][nf][0] + bv0) * outscale;
            float x1 = (acc[mi][nf][1] + bv1) * outscale;
            float y0 = (acc[mi][nf][2] + bv0) * outscale;
            float y1 = (acc[mi][nf][3] + bv1) * outscale;
            if (Ch) {
                ((uint32_t*)Ch)[((size_t)row * DKV + col) >> 1]       = pack_f16x2(x1, x0);
                ((uint32_t*)Ch)[((size_t)(row + 8) * DKV + col) >> 1] = pack_f16x2(y1, y0);
            } else {
                *(float2*)&Cf[(size_t)row * DKV + col]       = make_float2(x0, x1);
                *(float2*)&Cf[(size_t)(row + 8) * DKV + col] = make_float2(y0, y1);
            }
        }
    }
}

// ---------------------------------------------------------------------------
// Flash attention, full fp16 MMA path (m16n8k16): fp16 has the SAME 10-bit
// mantissa as tf32 (proven 2.1e-4 in R7) at half the MMA count.
// QK^T: Q/K fp16 tiles, XOR-swizzled, cp.async double-buffered K.
// PV:   P C-frag feeds A-frag directly (no shuffles); V packed fp16 key-pairs.
// Grid: (S/64, B), 256 threads (8 warps), 2 CTAs/SM. Split-key warps with
// one final merge. Smem = 66560 B.
// ---------------------------------------------------------------------------
#define VB_STR 136

__global__ __launch_bounds__(256, 2)
void attn_tc_kernel(float* __restrict__ out)
{
    extern __shared__ uint32_t smu[];
    uint32_t* Qs = smu;                    // 64 rows x 64 u32 (fp16x2), swizzled
    uint32_t* Ks = smu + 4096;             // 2 stages x 4096
    uint32_t* Vb = smu + 4096 + 8192;      // 32 pairs x VB_STR (fp16x2 key-pairs)

    const int b    = blockIdx.y;
    const int q0   = blockIdx.x * 64;
    const int tid  = threadIdx.x;
    const int lane = tid & 31;
    const int warp = tid >> 5;
    const int mg   = warp & 3;             // q-row group
    const int kh   = warp >> 2;            // key half (0/1)
    const int wm   = mg * 16;
    const int qg   = lane >> 2;
    const int qt   = lane & 3;

    const __half* qp = g_qph + (size_t)b * S_LEN * DKV;
    const __half* kp = g_kph + (size_t)b * S_LEN * DKV;
    const float*  vp = g_vp  + (size_t)b * S_LEN * DKV;

    // Prologue: cp.async Q tile + K tile 0 (16B chunks, XOR swizzle by row&7)
    #pragma unroll
    for (int i = 0; i < 4; i++) {
        int id  = tid + i * 256;           // 0..1023
        int row = id >> 4;                 // 0..63
        int c   = id & 15;                 // chunk (8 halves)
        cp16(smem_u32(&Qs[(row << 6) + ((c ^ (row & 7)) << 2)]),
             &qp[(size_t)(q0 + row) * DKV + (c << 3)]);
    }
    #pragma unroll
    for (int i = 0; i < 4; i++) {
        int id  = tid + i * 256;
        int row = id >> 4;
        int c   = id & 15;
        cp16(smem_u32(&Ks[(row << 6) + ((c ^ (row & 7)) << 2)]),
             &kp[(size_t)row * DKV + (c << 3)]);
    }
    CP_COMMIT();

    float o[16][4];
    #pragma unroll
    for (int d = 0; d < 16; d++)
        #pragma unroll
        for (int c = 0; c < 4; c++) o[d][c] = 0.0f;
    float m0 = -1e30f, m1 = -1e30f, l0 = 0.0f, l1 = 0.0f;

    for (int t = 0; t < S_LEN / 64; t++) {
        const int kt = t * 64;
        const int st = t & 1;

        // V tile -> registers (fp32), overlaps prior tile's compute
        float4 v0[4], v1[4];
        int vj[4], vd[4];
        #pragma unroll
        for (int i = 0; i < 4; i++) {
            int id = tid + i * 256;        // 0..1023
            vj[i] = id >> 5;               // key-pair 0..31
            vd[i] = (id & 31) << 2;        // d 0..124
            v0[i] = *(const float4*)&vp[(size_t)(kt + 2 * vj[i])     * DKV + vd[i]];
            v1[i] = *(const float4*)&vp[(size_t)(kt + 2 * vj[i] + 1) * DKV + vd[i]];
        }

        CP_WAIT(0);                        // K(t) resident
        __syncthreads();                   // prev PV done (Vb free), K(t) visible

        // issue K(t+1) into the other stage
        if (t + 1 < S_LEN / 64) {
            #pragma unroll
            for (int i = 0; i < 4; i++) {
                int id  = tid + i * 256;
                int row = id >> 4;
                int c   = id & 15;
                cp16(smem_u32(&Ks[(st ^ 1) * 4096 + (row << 6) + ((c ^ (row & 7)) << 2)]),
                     &kp[(size_t)(kt + 64 + row) * DKV + (c << 3)]);
            }
            CP_COMMIT();
        }

        // store V as fp16x2 key-pairs: Vb[j][d] = {lo=V[2j][d], hi=V[2j+1][d]}
        #pragma unroll
        for (int i = 0; i < 4; i++) {
            uint4 u;
            u.x = pack_f16x2(v1[i].x, v0[i].x);
            u.y = pack_f16x2(v1[i].y, v0[i].y);
            u.z = pack_f16x2(v1[i].z, v0[i].z);
            u.w = pack_f16x2(v1[i].w, v0[i].w);
            *(uint4*)&Vb[vj[i] * VB_STR + vd[i]] = u;
        }
        __syncthreads();                   // Vb ready

        const uint32_t* Ku = Ks + st * 4096;

        // ---- S = Q K^T (fp16, k16): 8 k-steps, 4 n-frags ----
        float s[4][4];
        #pragma unroll
        for (int nf = 0; nf < 4; nf++)
            #pragma unroll
            for (int c = 0; c < 4; c++) s[nf][c] = 0.0f;

        #pragma unroll
        for (int ks = 0; ks < 8; ks++) {
            const int c0 = (((2 * ks)     ^ qg) << 2) + qt;
            const int c1 = (((2 * ks + 1) ^ qg) << 2) + qt;
            uint32_t a0 = Qs[((wm + qg)     << 6) + c0];
            uint32_t a1 = Qs[((wm + qg + 8) << 6) + c0];
            uint32_t a2 = Qs[((wm + qg)     << 6) + c1];
            uint32_t a3 = Qs[((wm + qg + 8) << 6) + c1];
            #pragma unroll
            for (int nf = 0; nf < 4; nf++) {
                int kr = kh * 32 + nf * 8 + qg;
                uint32_t b0 = Ku[(kr << 6) + c0];
                uint32_t b1 = Ku[(kr << 6) + c1];
                mma_f16(s[nf][0], s[nf][1], s[nf][2], s[nf][3], a0, a1, a2, a3, b0, b1);
            }
        }

        // ---- online softmax (quad reduce across 4 lanes per row) ----
        float mx0 = -1e30f, mx1 = -1e30f;
        #pragma unroll
        for (int nf = 0; nf < 4; nf++) {
            mx0 = fmaxf(mx0, fmaxf(s[nf][0], s[nf][1]));
            mx1 = fmaxf(mx1, fmaxf(s[nf][2], s[nf][3]));
        }
        mx0 = fmaxf(mx0, __shfl_xor_sync(0xffffffffu, mx0, 1));
        mx0 = fmaxf(mx0, __shfl_xor_sync(0xffffffffu, mx0, 2));
        mx1 = fmaxf(mx1, __shfl_xor_sync(0xffffffffu, mx1, 1));
        mx1 = fmaxf(mx1, __shfl_xor_sync(0xffffffffu, mx1, 2));

        float mn0 = fmaxf(m0, mx0);
        float mn1 = fmaxf(m1, mx1);
        float alpha0 = __expf(m0 - mn0);
        float alpha1 = __expf(m1 - mn1);
        m0 = mn0; m1 = mn1;

        float ls0 = 0.0f, ls1 = 0.0f;
        #pragma unroll
        for (int nf = 0; nf < 4; nf++) {
            s[nf][0] = __expf(s[nf][0] - mn0);
            s[nf][1] = __expf(s[nf][1] - mn0);
            s[nf][2] = __expf(s[nf][2] - mn1);
            s[nf][3] = __expf(s[nf][3] - mn1);
            ls0 += s[nf][0] + s[nf][1];
            ls1 += s[nf][2] + s[nf][3];
        }
        ls0 += __shfl_xor_sync(0xffffffffu, ls0, 1);
        ls0 += __shfl_xor_sync(0xffffffffu, ls0, 2);
        ls1 += __shfl_xor_sync(0xffffffffu, ls1, 1);
        ls1 += __shfl_xor_sync(0xffffffffu, ls1, 2);
        l0 = l0 * alpha0 + ls0;
        l1 = l1 * alpha1 + ls1;

        #pragma unroll
        for (int d = 0; d < 16; d++) {
            o[d][0] *= alpha0; o[d][1] *= alpha0;
            o[d][2] *= alpha1; o[d][3] *= alpha1;
        }

        // ---- O += P V (fp16 m16n8k16): C-frag -> A-frag directly ----
        #pragma unroll
        for (int g = 0; g < 2; g++) {      // two 16-key groups in this half
            uint32_t a0 = pack_f16x2(s[2 * g][1],     s[2 * g][0]);
            uint32_t a1 = pack_f16x2(s[2 * g][3],     s[2 * g][2]);
            uint32_t a2 = pack_f16x2(s[2 * g + 1][1], s[2 * g + 1][0]);
            uint32_t a3 = pack_f16x2(s[2 * g + 1][3], s[2 * g + 1][2]);
            int j0 = kh * 16 + g * 8;
            #pragma unroll
            for (int df = 0; df < 16; df++) {
                uint32_t b0 = Vb[(j0 + qt)     * VB_STR + df * 8 + qg];
                uint32_t b1 = Vb[(j0 + qt + 4) * VB_STR + df * 8 + qg];
                mma_f16(o[df][0], o[df][1], o[df][2], o[df][3], a0, a1, a2, a3, b0, b1);
            }
        }
    }

    // ---- merge the two key-halves (reuse smem) ----
    __syncthreads();
    float* Ms = (float*)smu;               // 8192 floats (spans Qs + Ks stage 0)
    float* Lm = (float*)(smu + 8192);      // Ks stage 1 region
    float* Ll = Lm + 64;

    if (kh == 1) {
        #pragma unroll
        for (int df = 0; df < 16; df++) {
            int col = df * 8 + 2 * qt;
            Ms[mg * 2048 + qg * 128 + col]           = o[df][0];
            Ms[mg * 2048 + qg * 128 + col + 1]       = o[df][1];
            Ms[mg * 2048 + (qg + 8) * 128 + col]     = o[df][2];
            Ms[mg * 2048 + (qg + 8) * 128 + col + 1] = o[df][3];
        }
        if (qt == 0) {
            Lm[mg * 16 + qg]     = m0;  Ll[mg * 16 + qg]     = l0;
            Lm[mg * 16 + qg + 8] = m1;  Ll[mg * 16 + qg + 8] = l1;
        }
    }
    __syncthreads();

    if (kh == 0) {
        float mb0 = Lm[mg * 16 + qg],     lb0 = Ll[mg * 16 + qg];
        float mb1 = Lm[mg * 16 + qg + 8], lb1 = Ll[mg * 16 + qg + 8];
        float mn0 = fmaxf(m0, mb0), mn1 = fmaxf(m1, mb1);
        float ea0 = __expf(m0 - mn0),  eb0 = __expf(mb0 - mn0);
        float ea1 = __expf(m1 - mn1),  eb1 = __expf(mb1 - mn1);
        float inv0 = 1.0f / (l0 * ea0 + lb0 * eb0);
        float inv1 = 1.0f / (l1 * ea1 + lb1 * eb1);

        #pragma unroll
        for (int df = 0; df < 16; df++) {
            int col = df * 8 + 2 * qt;
            float ob0 = Ms[mg * 2048 + qg * 128 + col];
            float ob1 = Ms[mg * 2048 + qg * 128 + col + 1];
            float ob2 = Ms[mg * 2048 + (qg + 8) * 128 + col];
            float ob3 = Ms[mg * 2048 + (qg + 8) * 128 + col + 1];
            size_t row0 = (size_t)b * S_LEN + q0 + wm + qg;
            float2 w0, w1;
            w0.x = (o[df][0] * ea0 + ob0 * eb0) * inv0;
            w0.y = (o[df][1] * ea0 + ob1 * eb0) * inv0;
            w1.x = (o[df][2] * ea1 + ob2 * eb1) * inv1;
            w1.y = (o[df][3] * ea1 + ob3 * eb1) * inv1;
            *(float2*)&out[row0 * DKV + col]       = w0;
            *(float2*)&out[(row0 + 8) * DKV + col] = w1;
        }
    }
}

// ---------------------------------------------------------------------------
extern "C" void kernel_launch(void* const* d_in, const int* in_sizes, int n_in,
                              void* d_out, int out_size)
{
    const float* q  = (const float*)d_in[0];
    const float* k  = (const float*)d_in[1];
    const float* v  = (const float*)d_in[2];
    const float* wq = (const float*)d_in[3];
    const float* bq = (const float*)d_in[4];
    const float* wk = (const float*)d_in[5];
    const float* bk = (const float*)d_in[6];
    const float* wv = (const float*)d_in[7];
    const float* bv = (const float*)d_in[8];
    float* out = (float*)d_out;

    const int smem_bytes = (4096 + 8192 + 32 * VB_STR) * 4;   // 66560
    cudaFuncSetAttribute(attn_tc_kernel,
                         cudaFuncAttributeMaxDynamicSharedMemorySize, smem_bytes);

    proj_tc_kernel<<<dim3(128, 1, 3), 256>>>(q, k, v, wq, bq, wk, bk, wv, bv);
    attn_tc_kernel<<<dim3(S_LEN / 64, BATCH), 256, smem_bytes>>>(out);
}

// round 10
// speedup vs baseline: 6.6936x; 1.1991x over previous
#include <cuda_runtime.h>
#include <cuda_fp16.h>
#include <cstdint>

#define BATCH 4
#define S_LEN 4096
#define DM    1024
#define DKV   128

// Scratch (no cudaMalloc). Q/K projected -> fp16 (rn), Q pre-scaled by 1/sqrt(dk).
// V projected -> fp16 KEY-PAIR interleaved: g_vb[pair j][d] = {lo=V[2j][d], hi=V[2j+1][d]}
__device__ __half    g_qph[BATCH * S_LEN * DKV];
__device__ __half    g_kph[BATCH * S_LEN * DKV];
__device__ uint32_t  g_vb [BATCH * (S_LEN / 2) * DKV];

__device__ __forceinline__ uint32_t pack_f16x2(float hi, float lo) {
    uint32_t r;
    asm("cvt.rn.f16x2.f32 %0, %1, %2;" : "=r"(r) : "f"(hi), "f"(lo));
    return r;
}
__device__ __forceinline__ void cp16(uint32_t dst, const void* src) {
    asm volatile("cp.async.ca.shared.global [%0], [%1], 16;" :: "r"(dst), "l"(src) : "memory");
}
__device__ __forceinline__ uint32_t smem_u32(const void* p) {
    return (uint32_t)__cvta_generic_to_shared(p);
}
#define CP_COMMIT()  asm volatile("cp.async.commit_group;" ::: "memory")
#define CP_WAIT(n)   asm volatile("cp.async.wait_group %0;" :: "n"(n) : "memory")

__device__ __forceinline__ void mma_f16(float& d0, float& d1, float& d2, float& d3,
                                        uint32_t a0, uint32_t a1, uint32_t a2, uint32_t a3,
                                        uint32_t b0, uint32_t b1) {
    asm volatile(
        "mma.sync.aligned.m16n8k16.row.col.f32.f16.f16.f32 "
        "{%0,%1,%2,%3}, {%4,%5,%6,%7}, {%8,%9}, {%0,%1,%2,%3};"
        : "+f"(d0), "+f"(d1), "+f"(d2), "+f"(d3)
        : "r"(a0), "r"(a1), "r"(a2), "r"(a3), "r"(b0), "r"(b1));
}

// ---------------------------------------------------------------------------
// Projection GEMM via fp16 MMA (m16n8k16), register double-buffered LDG.
// C[16384,128] = A[16384,1024] @ W[1024,128] + bias.
// BM=128, BN=128, BK=32 (2 k16-steps/stage). 8 warps: 4 m-groups x 2 n-halves.
// A smem: [row][k-pair] u32, stride 20 (bank perm qg*20+qt).
// W smem: [k-pair][n]  u32, stride 136 (bank perm 8qt+qg).
// Epilogues: Q/K -> fp16 (Q scaled); V -> pair-interleaved fp16 (g_vb).
// ---------------------------------------------------------------------------
#define AT_STR 20
#define WT_STR 136

__global__ __launch_bounds__(256, 2)
void proj_tc_kernel(const float* __restrict__ q, const float* __restrict__ k,
                    const float* __restrict__ v,
                    const float* __restrict__ wq, const float* __restrict__ bq,
                    const float* __restrict__ wk, const float* __restrict__ bk,
                    const float* __restrict__ wv, const float* __restrict__ bv)
{
    const float* A; const float* W; const float* bias;
    __half* Ch = nullptr;
    if (blockIdx.z == 0)      { A = q; W = wq; bias = bq; Ch = g_qph; }
    else if (blockIdx.z == 1) { A = k; W = wk; bias = bk; Ch = g_kph; }
    else                      { A = v; W = wv; bias = bv; }
    const float outscale = (blockIdx.z == 0) ? 0.08838834764831845f : 1.0f;

    __shared__ uint32_t At[128 * AT_STR];   // 10240 B
    __shared__ uint32_t Wt[16 * WT_STR];    // 8704 B

    const int tid  = threadIdx.x;
    const int lane = tid & 31;
    const int warp = tid >> 5;
    const int mg   = warp >> 1;
    const int ng   = warp & 1;
    const int qg   = lane >> 2;
    const int qt   = lane & 3;
    const int m0   = blockIdx.x * 128;

    float acc[2][8][4];
    #pragma unroll
    for (int mi = 0; mi < 2; mi++)
        #pragma unroll
        for (int nf = 0; nf < 8; nf++)
            #pragma unroll
            for (int c = 0; c < 4; c++) acc[mi][nf][c] = 0.0f;

    float4 abuf[4], w0b[2], w1b[2];
    #pragma unroll
    for (int i = 0; i < 4; i++) {
        int id  = tid + i * 256;
        int row = id >> 3;                  // 0..127
        int kq  = (id & 7) << 2;            // 0..28
        abuf[i] = *(const float4*)&A[(size_t)(m0 + row) * DM + kq];
    }
    #pragma unroll
    for (int i = 0; i < 2; i++) {
        int id = tid + i * 256;
        int kp = id >> 5;                   // k-pair 0..15
        int n4 = (id & 31) << 2;            // 0..124
        w0b[i] = *(const float4*)&W[(size_t)(2 * kp)     * DKV + n4];
        w1b[i] = *(const float4*)&W[(size_t)(2 * kp + 1) * DKV + n4];
    }

    for (int k0 = 0; k0 < DM; k0 += 32) {
        __syncthreads();                    // previous stage's MMA reads done
        #pragma unroll
        for (int i = 0; i < 4; i++) {
            int id  = tid + i * 256;
            int row = id >> 3;
            int kq4 = id & 7;
            uint2 u = make_uint2(pack_f16x2(abuf[i].y, abuf[i].x),
                                 pack_f16x2(abuf[i].w, abuf[i].z));
            *(uint2*)&At[row * AT_STR + kq4 * 2] = u;
        }
        #pragma unroll
        for (int i = 0; i < 2; i++) {
            int id = tid + i * 256;
            int kp = id >> 5;
            int n4 = (id & 31) << 2;
            uint4 u = make_uint4(pack_f16x2(w1b[i].x, w0b[i].x),
                                 pack_f16x2(w1b[i].y, w0b[i].y),
                                 pack_f16x2(w1b[i].z, w0b[i].z),
                                 pack_f16x2(w1b[i].w, w0b[i].w));
            *(uint4*)&Wt[kp * WT_STR + n4] = u;
        }
        __syncthreads();

        if (k0 + 32 < DM) {                 // prefetch next stage (hidden under MMAs)
            #pragma unroll
            for (int i = 0; i < 4; i++) {
                int id  = tid + i * 256;
                int row = id >> 3;
                int kq  = (id & 7) << 2;
                abuf[i] = *(const float4*)&A[(size_t)(m0 + row) * DM + k0 + 32 + kq];
            }
            #pragma unroll
            for (int i = 0; i < 2; i++) {
                int id = tid + i * 256;
                int kp = id >> 5;
                int n4 = (id & 31) << 2;
                w0b[i] = *(const float4*)&W[(size_t)(k0 + 32 + 2 * kp)     * DKV + n4];
                w1b[i] = *(const float4*)&W[(size_t)(k0 + 32 + 2 * kp + 1) * DKV + n4];
            }
        }

        #pragma unroll
        for (int ks = 0; ks < 2; ks++) {
            uint32_t a[2][4];
            #pragma unroll
            for (int mi = 0; mi < 2; mi++) {
                int r = mg * 32 + mi * 16 + qg;
                a[mi][0] = At[r * AT_STR + ks * 8 + qt];
                a[mi][1] = At[(r + 8) * AT_STR + ks * 8 + qt];
                a[mi][2] = At[r * AT_STR + ks * 8 + qt + 4];
                a[mi][3] = At[(r + 8) * AT_STR + ks * 8 + qt + 4];
            }
            #pragma unroll
            for (int nf = 0; nf < 8; nf++) {
                uint32_t b0 = Wt[(ks * 8 + qt)     * WT_STR + ng * 64 + nf * 8 + qg];
                uint32_t b1 = Wt[(ks * 8 + qt + 4) * WT_STR + ng * 64 + nf * 8 + qg];
                #pragma unroll
                for (int mi = 0; mi < 2; mi++)
                    mma_f16(acc[mi][nf][0], acc[mi][nf][1], acc[mi][nf][2], acc[mi][nf][3],
                            a[mi][0], a[mi][1], a[mi][2], a[mi][3], b0, b1);
            }
        }
    }

    if (Ch) {
        // Q/K epilogue: bias + scale -> fp16
        #pragma unroll
        for (int nf = 0; nf < 8; nf++) {
            int col = ng * 64 + nf * 8 + 2 * qt;
            float bv0 = bias[col];
            float bv1 = bias[col + 1];
            #pragma unroll
            for (int mi = 0; mi < 2; mi++) {
                int row = m0 + mg * 32 + mi * 16 + qg;
                float x0 = (acc[mi][nf][0] + bv0) * outscale;
                float x1 = (acc[mi][nf][1] + bv1) * outscale;
                float y0 = (acc[mi][nf][2] + bv0) * outscale;
                float y1 = (acc[mi][nf][3] + bv1) * outscale;
                ((uint32_t*)Ch)[((size_t)row * DKV + col) >> 1]       = pack_f16x2(x1, x0);
                ((uint32_t*)Ch)[((size_t)(row + 8) * DKV + col) >> 1] = pack_f16x2(y1, y0);
            }
        }
    } else {
        // V epilogue: pair-interleave adjacent rows via lane^4 shuffles.
        // Rows qg (even) pair with qg+1; rows qg+8 pair with qg+9.
        #pragma unroll
        for (int nf = 0; nf < 8; nf++) {
            int col = ng * 64 + nf * 8 + 2 * qt;
            float bv0 = bias[col];
            float bv1 = bias[col + 1];
            #pragma unroll
            for (int mi = 0; mi < 2; mi++) {
                float x0 = acc[mi][nf][0] + bv0;
                float x1 = acc[mi][nf][1] + bv1;
                float y0 = acc[mi][nf][2] + bv0;
                float y1 = acc[mi][nf][3] + bv1;
                float px0 = __shfl_xor_sync(0xffffffffu, x0, 4);
                float px1 = __shfl_xor_sync(0xffffffffu, x1, 4);
                float py0 = __shfl_xor_sync(0xffffffffu, y0, 4);
                float py1 = __shfl_xor_sync(0xffffffffu, y1, 4);
                if (!(qg & 1)) {
                    int r = m0 + mg * 32 + mi * 16 + qg;      // even row
                    uint2 ux = make_uint2(pack_f16x2(px0, x0), pack_f16x2(px1, x1));
                    uint2 uy = make_uint2(pack_f16x2(py0, y0), pack_f16x2(py1, y1));
                    *(uint2*)&g_vb[(size_t)(r >> 1) * DKV + col]       = ux;
                    *(uint2*)&g_vb[(size_t)((r + 8) >> 1) * DKV + col] = uy;
                }
            }
        }
    }
}

// ---------------------------------------------------------------------------
// Flash attention, full fp16 MMA, cp.async double-buffered K AND V
// (V pre-interleaved by proj: zero per-tile conversion work).
// Grid: (S/64, B), 256 threads (8 warps), 2 CTAs/SM. Split-key warps,
// one merge at the end. Smem = 83968 B.
// Qs: 64x64 u32 XOR-swizzled | Ks: 2 x 64x64 u32 swizzled | Vb: 2 x 32x136 u32.
// ---------------------------------------------------------------------------
#define VB_STR 136

__global__ __launch_bounds__(256, 2)
void attn_tc_kernel(float* __restrict__ out)
{
    extern __shared__ uint32_t smu[];
    uint32_t* Qs = smu;                    // 4096
    uint32_t* Ks = smu + 4096;             // 2 x 4096
    uint32_t* Vb = smu + 4096 + 8192;      // 2 x 4352

    const int b    = blockIdx.y;
    const int q0   = blockIdx.x * 64;
    const int tid  = threadIdx.x;
    const int lane = tid & 31;
    const int warp = tid >> 5;
    const int mg   = warp & 3;             // q-row group
    const int kh   = warp >> 2;            // key half (0/1)
    const int wm   = mg * 16;
    const int qg   = lane >> 2;
    const int qt   = lane & 3;

    const __half*   qp  = g_qph + (size_t)b * S_LEN * DKV;
    const __half*   kp  = g_kph + (size_t)b * S_LEN * DKV;
    const uint32_t* vbp = g_vb  + (size_t)b * (S_LEN / 2) * DKV;

    // Prologue: Q + K0 + V0 (one commit group)
    #pragma unroll
    for (int i = 0; i < 4; i++) {
        int id  = tid + i * 256;
        int row = id >> 4;                 // 0..63
        int c   = id & 15;
        cp16(smem_u32(&Qs[(row << 6) + ((c ^ (row & 7)) << 2)]),
             &qp[(size_t)(q0 + row) * DKV + (c << 3)]);
    }
    #pragma unroll
    for (int i = 0; i < 4; i++) {
        int id  = tid + i * 256;
        int row = id >> 4;
        int c   = id & 15;
        cp16(smem_u32(&Ks[(row << 6) + ((c ^ (row & 7)) << 2)]),
             &kp[(size_t)row * DKV + (c << 3)]);
    }
    #pragma unroll
    for (int i = 0; i < 4; i++) {
        int id = tid + i * 256;
        int j  = id >> 5;                  // pair 0..31
        int c  = id & 31;
        cp16(smem_u32(&Vb[j * VB_STR + (c << 2)]),
             &vbp[(size_t)j * DKV + (c << 2)]);
    }
    CP_COMMIT();

    float o[16][4];
    #pragma unroll
    for (int d = 0; d < 16; d++)
        #pragma unroll
        for (int c = 0; c < 4; c++) o[d][c] = 0.0f;
    float m0 = -1e30f, m1 = -1e30f, l0 = 0.0f, l1 = 0.0f;

    for (int t = 0; t < S_LEN / 64; t++) {
        const int st = t & 1;

        CP_WAIT(0);                        // tile t's K/V resident (this thread)
        __syncthreads();                   // visible to all; prior compute done

        if (t + 1 < S_LEN / 64) {          // prefetch t+1 into the other stage
            const int kt2 = (t + 1) * 64;
            #pragma unroll
            for (int i = 0; i < 4; i++) {
                int id  = tid + i * 256;
                int row = id >> 4;
                int c   = id & 15;
                cp16(smem_u32(&Ks[(st ^ 1) * 4096 + (row << 6) + ((c ^ (row & 7)) << 2)]),
                     &kp[(size_t)(kt2 + row) * DKV + (c << 3)]);
            }
            #pragma unroll
            for (int i = 0; i < 4; i++) {
                int id = tid + i * 256;
                int j  = id >> 5;
                int c  = id & 31;
                cp16(smem_u32(&Vb[(st ^ 1) * 4352 + j * VB_STR + (c << 2)]),
                     &vbp[(size_t)(kt2 / 2 + j) * DKV + (c << 2)]);
            }
            CP_COMMIT();
        }

        const uint32_t* Ku = Ks + st * 4096;
        const uint32_t* Vu = Vb + st * 4352;

        // ---- S = Q K^T (fp16 k16): 8 k-steps, 4 n-frags ----
        float s[4][4];
        #pragma unroll
        for (int nf = 0; nf < 4; nf++)
            #pragma unroll
            for (int c = 0; c < 4; c++) s[nf][c] = 0.0f;

        #pragma unroll
        for (int ks = 0; ks < 8; ks++) {
            const int c0 = (((2 * ks)     ^ qg) << 2) + qt;
            const int c1 = (((2 * ks + 1) ^ qg) << 2) + qt;
            uint32_t a0 = Qs[((wm + qg)     << 6) + c0];
            uint32_t a1 = Qs[((wm + qg + 8) << 6) + c0];
            uint32_t a2 = Qs[((wm + qg)     << 6) + c1];
            uint32_t a3 = Qs[((wm + qg + 8) << 6) + c1];
            #pragma unroll
            for (int nf = 0; nf < 4; nf++) {
                int kr = kh * 32 + nf * 8 + qg;
                uint32_t b0 = Ku[(kr << 6) + c0];
                uint32_t b1 = Ku[(kr << 6) + c1];
                mma_f16(s[nf][0], s[nf][1], s[nf][2], s[nf][3], a0, a1, a2, a3, b0, b1);
            }
        }

        // ---- online softmax (quad reduce across 4 lanes per row) ----
        float mx0 = -1e30f, mx1 = -1e30f;
        #pragma unroll
        for (int nf = 0; nf < 4; nf++) {
            mx0 = fmaxf(mx0, fmaxf(s[nf][0], s[nf][1]));
            mx1 = fmaxf(mx1, fmaxf(s[nf][2], s[nf][3]));
        }
        mx0 = fmaxf(mx0, __shfl_xor_sync(0xffffffffu, mx0, 1));
        mx0 = fmaxf(mx0, __shfl_xor_sync(0xffffffffu, mx0, 2));
        mx1 = fmaxf(mx1, __shfl_xor_sync(0xffffffffu, mx1, 1));
        mx1 = fmaxf(mx1, __shfl_xor_sync(0xffffffffu, mx1, 2));

        float mn0 = fmaxf(m0, mx0);
        float mn1 = fmaxf(m1, mx1);
        float alpha0 = __expf(m0 - mn0);
        float alpha1 = __expf(m1 - mn1);
        m0 = mn0; m1 = mn1;

        float ls0 = 0.0f, ls1 = 0.0f;
        #pragma unroll
        for (int nf = 0; nf < 4; nf++) {
            s[nf][0] = __expf(s[nf][0] - mn0);
            s[nf][1] = __expf(s[nf][1] - mn0);
            s[nf][2] = __expf(s[nf][2] - mn1);
            s[nf][3] = __expf(s[nf][3] - mn1);
            ls0 += s[nf][0] + s[nf][1];
            ls1 += s[nf][2] + s[nf][3];
        }
        ls0 += __shfl_xor_sync(0xffffffffu, ls0, 1);
        ls0 += __shfl_xor_sync(0xffffffffu, ls0, 2);
        ls1 += __shfl_xor_sync(0xffffffffu, ls1, 1);
        ls1 += __shfl_xor_sync(0xffffffffu, ls1, 2);
        l0 = l0 * alpha0 + ls0;
        l1 = l1 * alpha1 + ls1;

        #pragma unroll
        for (int d = 0; d < 16; d++) {
            o[d][0] *= alpha0; o[d][1] *= alpha0;
            o[d][2] *= alpha1; o[d][3] *= alpha1;
        }

        // ---- O += P V (fp16): P C-frag feeds A-frag directly ----
        #pragma unroll
        for (int g = 0; g < 2; g++) {
            uint32_t a0 = pack_f16x2(s[2 * g][1],     s[2 * g][0]);
            uint32_t a1 = pack_f16x2(s[2 * g][3],     s[2 * g][2]);
            uint32_t a2 = pack_f16x2(s[2 * g + 1][1], s[2 * g + 1][0]);
            uint32_t a3 = pack_f16x2(s[2 * g + 1][3], s[2 * g + 1][2]);
            int j0 = kh * 16 + g * 8;
            #pragma unroll
            for (int df = 0; df < 16; df++) {
                uint32_t b0 = Vu[(j0 + qt)     * VB_STR + df * 8 + qg];
                uint32_t b1 = Vu[(j0 + qt + 4) * VB_STR + df * 8 + qg];
                mma_f16(o[df][0], o[df][1], o[df][2], o[df][3], a0, a1, a2, a3, b0, b1);
            }
        }
    }

    // ---- merge the two key-halves (reuse smem) ----
    __syncthreads();
    float* Ms = (float*)smu;               // 8192 floats (Qs + Ks stage 0)
    float* Lm = (float*)(smu + 8192);      // Ks stage 1 region
    float* Ll = Lm + 64;

    if (kh == 1) {
        #pragma unroll
        for (int df = 0; df < 16; df++) {
            int col = df * 8 + 2 * qt;
            Ms[mg * 2048 + qg * 128 + col]           = o[df][0];
            Ms[mg * 2048 + qg * 128 + col + 1]       = o[df][1];
            Ms[mg * 2048 + (qg + 8) * 128 + col]     = o[df][2];
            Ms[mg * 2048 + (qg + 8) * 128 + col + 1] = o[df][3];
        }
        if (qt == 0) {
            Lm[mg * 16 + qg]     = m0;  Ll[mg * 16 + qg]     = l0;
            Lm[mg * 16 + qg + 8] = m1;  Ll[mg * 16 + qg + 8] = l1;
        }
    }
    __syncthreads();

    if (kh == 0) {
        float mb0 = Lm[mg * 16 + qg],     lb0 = Ll[mg * 16 + qg];
        float mb1 = Lm[mg * 16 + qg + 8], lb1 = Ll[mg * 16 + qg + 8];
        float mn0 = fmaxf(m0, mb0), mn1 = fmaxf(m1, mb1);
        float ea0 = __expf(m0 - mn0),  eb0 = __expf(mb0 - mn0);
        float ea1 = __expf(m1 - mn1),  eb1 = __expf(mb1 - mn1);
        float inv0 = 1.0f / (l0 * ea0 + lb0 * eb0);
        float inv1 = 1.0f / (l1 * ea1 + lb1 * eb1);

        #pragma unroll
        for (int df = 0; df < 16; df++) {
            int col = df * 8 + 2 * qt;
            float ob0 = Ms[mg * 2048 + qg * 128 + col];
            float ob1 = Ms[mg * 2048 + qg * 128 + col + 1];
            float ob2 = Ms[mg * 2048 + (qg + 8) * 128 + col];
            float ob3 = Ms[mg * 2048 + (qg + 8) * 128 + col + 1];
            size_t row0 = (size_t)b * S_LEN + q0 + wm + qg;
            float2 w0, w1;
            w0.x = (o[df][0] * ea0 + ob0 * eb0) * inv0;
            w0.y = (o[df][1] * ea0 + ob1 * eb0) * inv0;
            w1.x = (o[df][2] * ea1 + ob2 * eb1) * inv1;
            w1.y = (o[df][3] * ea1 + ob3 * eb1) * inv1;
            *(float2*)&out[row0 * DKV + col]       = w0;
            *(float2*)&out[(row0 + 8) * DKV + col] = w1;
        }
    }
}

// ---------------------------------------------------------------------------
extern "C" void kernel_launch(void* const* d_in, const int* in_sizes, int n_in,
                              void* d_out, int out_size)
{
    const float* q  = (const float*)d_in[0];
    const float* k  = (const float*)d_in[1];
    const float* v  = (const float*)d_in[2];
    const float* wq = (const float*)d_in[3];
    const float* bq = (const float*)d_in[4];
    const float* wk = (const float*)d_in[5];
    const float* bk = (const float*)d_in[6];
    const float* wv = (const float*)d_in[7];
    const float* bv = (const float*)d_in[8];
    float* out = (float*)d_out;

    const int smem_bytes = (4096 + 8192 + 2 * 4352) * 4;   // 83968
    cudaFuncSetAttribute(attn_tc_kernel,
                         cudaFuncAttributeMaxDynamicSharedMemorySize, smem_bytes);

    proj_tc_kernel<<<dim3(128, 1, 3), 256>>>(q, k, v, wq, bq, wk, bk, wv, bv);
    attn_tc_kernel<<<dim3(S_LEN / 64, BATCH), 256, smem_bytes>>>(out);
}